// round 14
// baseline (speedup 1.0000x reference)
#include <cuda_runtime.h>
#include <cstdint>

#define NUM_IN 25
#define NUM_OUT 20
#define J_PAIRS 13

typedef unsigned long long u64;

// Constant bank: all packed weights (constant port / LDC only).
struct __align__(16) CParams {
    u64 w1[25][14];  // [k][jp] = {W1[2jp][k], W1[2jp+1][k]}
    u64 b1[14];
    u64 w2[25][10];  // [k][ip] = {W2[2ip][k], W2[2ip+1][k]}
    u64 b2[10];
};
__constant__ CParams cP;

__device__ __forceinline__ u64 dpack(float lo, float hi) {
    return (u64)__float_as_uint(lo) | ((u64)__float_as_uint(hi) << 32);
}
__device__ __forceinline__ u64 pk2s(float v) {
    u64 r;
    asm("mov.b64 %0, {%1, %1};" : "=l"(r) : "f"(v));
    return r;
}
__device__ __forceinline__ void upk2(u64 v, float& lo, float& hi) {
    asm("mov.b64 {%0, %1}, %2;" : "=f"(lo), "=f"(hi) : "l"(v));
}
__device__ __forceinline__ u64 ffma2(u64 a, u64 b, u64 c) {
    u64 d;
    asm("fma.rn.f32x2 %0, %1, %2, %3;" : "=l"(d) : "l"(a), "l"(b), "l"(c));
    return d;
}

// ---- Prep: pack weights straight into cP's backing store ----
__global__ void prep_kernel(CParams* __restrict__ cp,
                            const float* __restrict__ W1, const float* __restrict__ b1,
                            const float* __restrict__ W2, const float* __restrict__ b2)
{
    int t = threadIdx.x;
    int stride = blockDim.x;
    for (int i = t; i < 25 * 14; i += stride) {
        int k = i / 14, jp = i % 14;
        float lo = 0.0f, hi = 0.0f;
        if (jp < J_PAIRS) {
            lo = W1[(2 * jp) * NUM_IN + k];
            if (2 * jp + 1 < NUM_IN) hi = W1[(2 * jp + 1) * NUM_IN + k];
        }
        cp->w1[k][jp] = dpack(lo, hi);
    }
    for (int i = t; i < 14; i += stride) {
        float lo = 0.0f, hi = 0.0f;
        if (i < J_PAIRS) {
            lo = b1[2 * i];
            if (2 * i + 1 < NUM_IN) hi = b1[2 * i + 1];
        }
        cp->b1[i] = dpack(lo, hi);
    }
    for (int i = t; i < 25 * 10; i += stride) {
        int k = i / 10, ip = i % 10;
        cp->w2[k][ip] = dpack(W2[(2 * ip) * NUM_IN + k], W2[(2 * ip + 1) * NUM_IN + k]);
    }
    for (int i = t; i < 10; i += stride)
        cp->b2[i] = dpack(b2[2 * i], b2[2 * i + 1]);
}

// Layer-1 partial over k in [K0,K1), 3 edges share each weight load.
template <int K0, int K1>
__device__ __forceinline__ void l1_phase3(const float (&xa)[K1 - K0],
                                          const float (&xb)[K1 - K0],
                                          const float (&xc)[K1 - K0],
                                          u64 (&acc0)[J_PAIRS],
                                          u64 (&acc1)[J_PAIRS],
                                          u64 (&acc2)[J_PAIRS])
{
    #pragma unroll
    for (int k = K0; k < K1; k++) {
        u64 x0 = pk2s(xa[k - K0]);
        u64 x1 = pk2s(xb[k - K0]);
        u64 x2 = pk2s(xc[k - K0]);
        const ulonglong2* wv = reinterpret_cast<const ulonglong2*>(cP.w1[k]);
        #pragma unroll
        for (int q = 0; q < 6; q++) {
            ulonglong2 w = wv[q];
            acc0[2 * q]     = ffma2(w.x, x0, acc0[2 * q]);
            acc1[2 * q]     = ffma2(w.x, x1, acc1[2 * q]);
            acc2[2 * q]     = ffma2(w.x, x2, acc2[2 * q]);
            acc0[2 * q + 1] = ffma2(w.y, x0, acc0[2 * q + 1]);
            acc1[2 * q + 1] = ffma2(w.y, x1, acc1[2 * q + 1]);
            acc2[2 * q + 1] = ffma2(w.y, x2, acc2[2 * q + 1]);
        }
        u64 w12 = cP.w1[k][12];
        acc0[12] = ffma2(w12, x0, acc0[12]);
        acc1[12] = ffma2(w12, x1, acc1[12]);
        acc2[12] = ffma2(w12, x2, acc2[12]);
    }
}

// Layer-2 chunk over vec-pair range [Q0,Q1): output rows 4*Q0..4*Q1-1, 3 edges.
template <int Q0, int Q1>
__device__ __forceinline__ void l2_chunk3(const float (&ya)[26], const float (&yb)[26],
                                          const float (&yc)[26],
                                          float (&za)[4 * (Q1 - Q0)],
                                          float (&zb)[4 * (Q1 - Q0)],
                                          float (&zc)[4 * (Q1 - Q0)])
{
    constexpr int NP = 2 * (Q1 - Q0);
    u64 z0[NP], z1[NP], z2[NP];
    {
        const ulonglong2* bv = reinterpret_cast<const ulonglong2*>(cP.b2);
        #pragma unroll
        for (int q = Q0; q < Q1; q++) {
            ulonglong2 b = bv[q];
            z0[2 * (q - Q0)]     = b.x; z1[2 * (q - Q0)]     = b.x; z2[2 * (q - Q0)]     = b.x;
            z0[2 * (q - Q0) + 1] = b.y; z1[2 * (q - Q0) + 1] = b.y; z2[2 * (q - Q0) + 1] = b.y;
        }
    }
    #pragma unroll
    for (int k = 0; k < NUM_IN; k++) {
        u64 y0 = pk2s(ya[k]);
        u64 y1 = pk2s(yb[k]);
        u64 y2 = pk2s(yc[k]);
        #pragma unroll
        for (int q = Q0; q < Q1; q++) {
            ulonglong2 w = *reinterpret_cast<const ulonglong2*>(&cP.w2[k][2 * q]);
            z0[2 * (q - Q0)]     = ffma2(w.x, y0, z0[2 * (q - Q0)]);
            z1[2 * (q - Q0)]     = ffma2(w.x, y1, z1[2 * (q - Q0)]);
            z2[2 * (q - Q0)]     = ffma2(w.x, y2, z2[2 * (q - Q0)]);
            z0[2 * (q - Q0) + 1] = ffma2(w.y, y0, z0[2 * (q - Q0) + 1]);
            z1[2 * (q - Q0) + 1] = ffma2(w.y, y1, z1[2 * (q - Q0) + 1]);
            z2[2 * (q - Q0) + 1] = ffma2(w.y, y2, z2[2 * (q - Q0) + 1]);
        }
    }
    #pragma unroll
    for (int p = 0; p < NP; p++) {
        float lo, hi;
        upk2(z0[p], lo, hi);
        za[2 * p] = fmaxf(lo, 0.0f); za[2 * p + 1] = fmaxf(hi, 0.0f);
        upk2(z1[p], lo, hi);
        zb[2 * p] = fmaxf(lo, 0.0f); zb[2 * p + 1] = fmaxf(hi, 0.0f);
        upk2(z2[p], lo, hi);
        zc[2 * p] = fmaxf(lo, 0.0f); zc[2 * p + 1] = fmaxf(hi, 0.0f);
    }
}

// ---- Main: 3 edges/thread, all weights via constant port ----
__global__ void __launch_bounds__(128, 4)
edge_mlp_kernel(const float* __restrict__ r,
                const float* __restrict__ a_data,
                const float* __restrict__ a_material,
                const float* __restrict__ a_influx,
                const float* __restrict__ b_data,
                const float* __restrict__ b_material,
                const float* __restrict__ b_influx,
                const float* __restrict__ e_data,
                float* __restrict__ out,
                int E)
{
    long idx = (long)blockIdx.x * blockDim.x + threadIdx.x;
    long e0 = idx * 3;
    if (e0 >= E) return;
    bool have1 = (e0 + 1 < E);
    bool have2 = (e0 + 2 < E);
    long e1 = have1 ? (e0 + 1) : e0;
    long e2 = have2 ? (e0 + 2) : e0;

    const float4* ad4 = reinterpret_cast<const float4*>(a_data);
    const float4* bd4 = reinterpret_cast<const float4*>(b_data);
    const float4* ed4 = reinterpret_cast<const float4*>(e_data);

    u64 acc0[J_PAIRS], acc1[J_PAIRS], acc2[J_PAIRS];
    #pragma unroll
    for (int p = 0; p < J_PAIRS; p++) {
        u64 b = cP.b1[p];
        acc0[p] = b; acc1[p] = b; acc2[p] = b;
    }

    // Phase A1: feats 0..8 (r + a_data)
    {
        float xa[9], xb[9], xc[9];
        xa[0] = r[e0]; xb[0] = r[e1]; xc[0] = r[e2];
        float4 p = ad4[2 * e0], q = ad4[2 * e1], s = ad4[2 * e2];
        xa[1] = p.x; xa[2] = p.y; xa[3] = p.z; xa[4] = p.w;
        xb[1] = q.x; xb[2] = q.y; xb[3] = q.z; xb[4] = q.w;
        xc[1] = s.x; xc[2] = s.y; xc[3] = s.z; xc[4] = s.w;
        p = ad4[2 * e0 + 1]; q = ad4[2 * e1 + 1]; s = ad4[2 * e2 + 1];
        xa[5] = p.x; xa[6] = p.y; xa[7] = p.z; xa[8] = p.w;
        xb[5] = q.x; xb[6] = q.y; xb[7] = q.z; xb[8] = q.w;
        xc[5] = s.x; xc[6] = s.y; xc[7] = s.z; xc[8] = s.w;
        l1_phase3<0, 9>(xa, xb, xc, acc0, acc1, acc2);
    }
    // Phase A2: feats 9,10
    {
        float xa[2], xb[2], xc[2];
        xa[0] = a_material[e0]; xb[0] = a_material[e1]; xc[0] = a_material[e2];
        xa[1] = a_influx[e0];   xb[1] = a_influx[e1];   xc[1] = a_influx[e2];
        l1_phase3<9, 11>(xa, xb, xc, acc0, acc1, acc2);
    }
    // Phase B1: feats 11..18 (b_data)
    {
        float xa[8], xb[8], xc[8];
        float4 p = bd4[2 * e0], q = bd4[2 * e1], s = bd4[2 * e2];
        xa[0] = p.x; xa[1] = p.y; xa[2] = p.z; xa[3] = p.w;
        xb[0] = q.x; xb[1] = q.y; xb[2] = q.z; xb[3] = q.w;
        xc[0] = s.x; xc[1] = s.y; xc[2] = s.z; xc[3] = s.w;
        p = bd4[2 * e0 + 1]; q = bd4[2 * e1 + 1]; s = bd4[2 * e2 + 1];
        xa[4] = p.x; xa[5] = p.y; xa[6] = p.z; xa[7] = p.w;
        xb[4] = q.x; xb[5] = q.y; xb[6] = q.z; xb[7] = q.w;
        xc[4] = s.x; xc[5] = s.y; xc[6] = s.z; xc[7] = s.w;
        l1_phase3<11, 19>(xa, xb, xc, acc0, acc1, acc2);
    }
    // Phase B2: feats 19,20
    {
        float xa[2], xb[2], xc[2];
        xa[0] = b_material[e0]; xb[0] = b_material[e1]; xc[0] = b_material[e2];
        xa[1] = b_influx[e0];   xb[1] = b_influx[e1];   xc[1] = b_influx[e2];
        l1_phase3<19, 21>(xa, xb, xc, acc0, acc1, acc2);
    }
    // Phase B3: feats 21..24 (e_data)
    {
        float xa[4], xb[4], xc[4];
        float4 p = ed4[e0], q = ed4[e1], s = ed4[e2];
        xa[0] = p.x; xa[1] = p.y; xa[2] = p.z; xa[3] = p.w;
        xb[0] = q.x; xb[1] = q.y; xb[2] = q.z; xb[3] = q.w;
        xc[0] = s.x; xc[1] = s.y; xc[2] = s.z; xc[3] = s.w;
        l1_phase3<21, 25>(xa, xb, xc, acc0, acc1, acc2);
    }

    // ReLU -> y (scalar, feeds layer-2 splats)
    float ya[26], yb[26], yc[26];
    #pragma unroll
    for (int p = 0; p < J_PAIRS; p++) {
        float lo, hi;
        upk2(acc0[p], lo, hi);
        ya[2 * p] = fmaxf(lo, 0.0f); ya[2 * p + 1] = fmaxf(hi, 0.0f);
        upk2(acc1[p], lo, hi);
        yb[2 * p] = fmaxf(lo, 0.0f); yb[2 * p + 1] = fmaxf(hi, 0.0f);
        upk2(acc2[p], lo, hi);
        yc[2 * p] = fmaxf(lo, 0.0f); yc[2 * p + 1] = fmaxf(hi, 0.0f);
    }

    float4* ov = reinterpret_cast<float4*>(out);
    long Ef4_b1 = 2L * (long)E;
    long Ef4_b2 = 4L * (long)E;

    // Chunk A: rows 0..7 -> block 0
    {
        float za[8], zb[8], zc[8];
        l2_chunk3<0, 2>(ya, yb, yc, za, zb, zc);
        ov[2 * e0]     = make_float4(za[0], za[1], za[2], za[3]);
        ov[2 * e0 + 1] = make_float4(za[4], za[5], za[6], za[7]);
        if (have1) {
            ov[2 * e1]     = make_float4(zb[0], zb[1], zb[2], zb[3]);
            ov[2 * e1 + 1] = make_float4(zb[4], zb[5], zb[6], zb[7]);
        }
        if (have2) {
            ov[2 * e2]     = make_float4(zc[0], zc[1], zc[2], zc[3]);
            ov[2 * e2 + 1] = make_float4(zc[4], zc[5], zc[6], zc[7]);
        }
    }
    // Chunk B: rows 8..15 -> block 1
    {
        float za[8], zb[8], zc[8];
        l2_chunk3<2, 4>(ya, yb, yc, za, zb, zc);
        ov[Ef4_b1 + 2 * e0]     = make_float4(za[0], za[1], za[2], za[3]);
        ov[Ef4_b1 + 2 * e0 + 1] = make_float4(za[4], za[5], za[6], za[7]);
        if (have1) {
            ov[Ef4_b1 + 2 * e1]     = make_float4(zb[0], zb[1], zb[2], zb[3]);
            ov[Ef4_b1 + 2 * e1 + 1] = make_float4(zb[4], zb[5], zb[6], zb[7]);
        }
        if (have2) {
            ov[Ef4_b1 + 2 * e2]     = make_float4(zc[0], zc[1], zc[2], zc[3]);
            ov[Ef4_b1 + 2 * e2 + 1] = make_float4(zc[4], zc[5], zc[6], zc[7]);
        }
    }
    // Chunk C: rows 16..19 -> block 2
    {
        float za[4], zb[4], zc[4];
        l2_chunk3<4, 5>(ya, yb, yc, za, zb, zc);
        ov[Ef4_b2 + e0] = make_float4(za[0], za[1], za[2], za[3]);
        if (have1) ov[Ef4_b2 + e1] = make_float4(zb[0], zb[1], zb[2], zb[3]);
        if (have2) ov[Ef4_b2 + e2] = make_float4(zc[0], zc[1], zc[2], zc[3]);
    }
}

extern "C" void kernel_launch(void* const* d_in, const int* in_sizes, int n_in,
                              void* d_out, int out_size)
{
    const float* r          = (const float*)d_in[0];
    const float* a_data     = (const float*)d_in[1];
    const float* a_material = (const float*)d_in[2];
    const float* a_influx   = (const float*)d_in[3];
    const float* b_data     = (const float*)d_in[4];
    const float* b_material = (const float*)d_in[5];
    const float* b_influx   = (const float*)d_in[6];
    const float* e_data     = (const float*)d_in[7];
    const float* W1         = (const float*)d_in[8];
    const float* b1         = (const float*)d_in[9];
    const float* W2         = (const float*)d_in[10];
    const float* b2         = (const float*)d_in[11];
    float* out = (float*)d_out;

    int E = in_sizes[0];

    void* cp_addr = nullptr;
    cudaGetSymbolAddress(&cp_addr, cP);
    prep_kernel<<<1, 256>>>((CParams*)cp_addr, W1, b1, W2, b2);

    long triples = ((long)E + 2) / 3;
    int threads = 128;
    int blocks = (int)((triples + threads - 1) / threads);
    edge_mlp_kernel<<<blocks, threads>>>(r, a_data, a_material, a_influx,
                                         b_data, b_material, b_influx, e_data,
                                         out, E);
}